// round 6
// baseline (speedup 1.0000x reference)
#include <cuda_runtime.h>

// Problem constants (fixed by the reference).
#define Bn 4096
#define Tn 2048
#define Hn 64

// Per-block partial loss sums (no alloc allowed -> device global scratch).
__device__ float g_partial[Bn];

// ---------- packed f32x2 helpers (FFMA2 path, sm_103a) ----------
__device__ __forceinline__ unsigned long long pack2(float x, float y) {
    unsigned long long r;
    asm("mov.b64 %0, {%1, %2};" : "=l"(r) : "f"(x), "f"(y));
    return r;
}
__device__ __forceinline__ void unpack2(unsigned long long v, float& x, float& y) {
    asm("mov.b64 {%0, %1}, %2;" : "=f"(x), "=f"(y) : "l"(v));
}
__device__ __forceinline__ void ffma2(unsigned long long& d,
                                      unsigned long long a,
                                      unsigned long long b) {
    asm("fma.rn.f32x2 %0, %1, %2, %0;" : "+l"(d) : "l"(a), "l"(b));
}
__device__ __forceinline__ unsigned long long add2(unsigned long long a,
                                                   unsigned long long b) {
    unsigned long long r;
    asm("add.rn.f32x2 %0, %1, %2;" : "=l"(r) : "l"(a), "l"(b));
    return r;
}

// ---------- activations: hardware MUFU.TANH ----------
__device__ __forceinline__ float tanh_hw(float x) {
    float r;
    asm("tanh.approx.f32 %0, %1;" : "=f"(r) : "f"(x));
    return r;
}
__device__ __forceinline__ float sigm(float x) {
    return __fmaf_rn(tanh_hw(0.5f * x), 0.5f, 0.5f);
}

// ---------- padded copy: out[1 .. 1+B*T) = padded ----------
__global__ void copy_pad_kernel(const float4* __restrict__ src,
                                float* __restrict__ dst, int n4) {
    int i = blockIdx.x * blockDim.x + threadIdx.x;
    if (i < n4) {
        float4 v = src[i];
        int j = 4 * i;
        dst[j + 0] = v.x;
        dst[j + 1] = v.y;
        dst[j + 2] = v.z;
        dst[j + 3] = v.w;
    }
}

// no-op padding kernels so ncu's -s 5 -c 1 lands on lstm_kernel next capture
__global__ void nop_kernel() {}

// ---------- main LSTM kernel: one CTA (128 threads) per batch element ----------
// Thread pair (2u, 2u+1) owns hidden unit u:
//   even thread: gate rows (u, 64+u)      = (i, f)
//   odd  thread: gate rows (128+u, 192+u) = (g, o)
// One barrier per step; h kept in a 4-deep ring so the y-projection of step
// s-1 can be computed lazily by warp (s-1)&3 (rotates the side work).
__global__ __launch_bounds__(128, 3)
void lstm_kernel(const float* __restrict__ padded,
                 const int*   __restrict__ seq_lengths,
                 const float* __restrict__ enc_Wih,
                 const float* __restrict__ enc_Whh,
                 const float* __restrict__ enc_b,
                 const float* __restrict__ enc_linW,
                 const float* __restrict__ enc_linb,
                 const float* __restrict__ dec_linW,
                 const float* __restrict__ dec_linb,
                 const float* __restrict__ dec_Wih,
                 const float* __restrict__ dec_Whh,
                 const float* __restrict__ dec_b,
                 const float* __restrict__ outW,
                 const float* __restrict__ outb,
                 float* __restrict__ out) {
    __shared__ float4 hb4[4][Hn / 4];   // 4-deep ring of hidden states
    __shared__ float4 sh_ow4[Hn / 4];   // outW staged for decoder fold
    __shared__ float  xbuf[Tn];         // input sequence
    __shared__ float  sh_s[4];          // bottleneck hz / loss partials

    const int  b    = blockIdx.x;
    const int  t    = threadIdx.x;
    const int  u    = t >> 1;
    const bool even = !(t & 1);
    const int  lane = t & 31;
    const int  wid  = t >> 5;

    float* hb0   = (float*)hb4[0];
    float* sh_ow = (float*)sh_ow4;

    const int rA = even ? u      : 128 + u;
    const int rB = even ? 64 + u : 192 + u;

    // Prefetch input sequence + init state + stage outW.
    const float* xin = padded + (size_t)b * Tn;
    for (int i = t; i < Tn; i += 128) xbuf[i] = xin[i];
    if (t < Hn) { hb0[t] = 0.0f; sh_ow[t] = outW[t]; }

    const int seqlen = seq_lengths[b];

    // Encoder weights -> registers (2 rows x 64 = 64 f32x2 pairs).
    unsigned long long wA[32], wB[32];
    {
        const float4* pA = (const float4*)(enc_Whh + rA * Hn);
        const float4* pB = (const float4*)(enc_Whh + rB * Hn);
#pragma unroll
        for (int k = 0; k < 16; k++) {
            float4 a = pA[k];
            wA[2 * k]     = pack2(a.x, a.y);
            wA[2 * k + 1] = pack2(a.z, a.w);
            float4 c = pB[k];
            wB[2 * k]     = pack2(c.x, c.y);
            wB[2 * k + 1] = pack2(c.z, c.w);
        }
    }
    float wihA = enc_Wih[rA], wihB = enc_Wih[rB];
    float bsA  = enc_b[rA],   bsB  = enc_b[rB];
    float c_reg = 0.0f;                 // cell state (replicated in pair)

    __syncthreads();

    // ---- encoder: state freezes at seqlen -> stop there ----
    for (int s = 0; s < seqlen; s++) {
        const ulonglong2* hq = (const ulonglong2*)hb4[s & 3];
        float* wout = (float*)hb4[(s + 1) & 3];

        unsigned long long aA0 = 0ull, aA1 = 0ull, aB0 = 0ull, aB1 = 0ull;
#pragma unroll
        for (int k = 0; k < 16; k++) {
            ulonglong2 hv = hq[k];      // broadcast LDS.128
            ffma2(aA0, wA[2 * k],     hv.x);
            ffma2(aA1, wA[2 * k + 1], hv.y);
            ffma2(aB0, wB[2 * k],     hv.x);
            ffma2(aB1, wB[2 * k + 1], hv.y);
        }
        float x = xbuf[s];
        float sA0, sA1, sB0, sB1;
        unpack2(add2(aA0, aA1), sA0, sA1);
        unpack2(add2(aB0, aB1), sB0, sB1);
        float gA = (sA0 + sA1) + __fmaf_rn(x, wihA, bsA);
        float gB = (sB0 + sB1) + __fmaf_rn(x, wihB, bsB);

        float oA = __shfl_xor_sync(0xffffffffu, gA, 1);
        float oB = __shfl_xor_sync(0xffffffffu, gB, 1);
        float gi = even ? gA : oA;
        float gf = even ? gB : oB;
        float gg = even ? oA : gA;
        float go = even ? oB : gB;

        c_reg   = sigm(gf) * c_reg + sigm(gi) * tanh_hw(gg);
        float h = sigm(go) * tanh_hw(c_reg);
        if (even) wout[u] = h;
        __syncthreads();
    }

    // ---- bottleneck: hz = sigmoid(h @ enc_linW.T + enc_linb) ----
    const float* hfin = (const float*)hb4[seqlen & 3];
    if (t < 3) {
        float s = enc_linb[t];
        const float* wl = enc_linW + t * Hn;
#pragma unroll 16
        for (int j = 0; j < Hn; j++) s = __fmaf_rn(wl[j], hfin[j], s);
        float z = sigm(s);
        sh_s[t] = z;
        out[1 + 2 * (size_t)Bn * Tn + (size_t)b * 3 + t] = z;
    }
    __syncthreads();

    // hd = hz @ dec_linW.T + dec_linb  (into ring slot 0; c carries over)
    float hd_z0 = sh_s[0], hd_z1 = sh_s[1], hd_z2 = sh_s[2];
    __syncthreads();                    // done reading hfin before overwrite
    if (t < Hn) {
        hb0[t] = dec_linb[t]
               + dec_linW[t * 3 + 0] * hd_z0
               + dec_linW[t * 3 + 1] * hd_z1
               + dec_linW[t * 3 + 2] * hd_z2;
    }

    // Decoder weights, FOLDED: W' = dec_Whh + dec_Wih (x) outW,
    // b' = dec_b + dec_Wih*outb.  Removes y->x from the critical path.
    float wihA2 = dec_Wih[rA], wihB2 = dec_Wih[rB];
    {
        const float4* pA = (const float4*)(dec_Whh + rA * Hn);
        const float4* pB = (const float4*)(dec_Whh + rB * Hn);
#pragma unroll
        for (int k = 0; k < 16; k++) {
            float4 a = pA[k], c = pB[k], o = sh_ow4[k];
            wA[2 * k]     = pack2(__fmaf_rn(wihA2, o.x, a.x), __fmaf_rn(wihA2, o.y, a.y));
            wA[2 * k + 1] = pack2(__fmaf_rn(wihA2, o.z, a.z), __fmaf_rn(wihA2, o.w, a.w));
            wB[2 * k]     = pack2(__fmaf_rn(wihB2, o.x, c.x), __fmaf_rn(wihB2, o.y, c.y));
            wB[2 * k + 1] = pack2(__fmaf_rn(wihB2, o.z, c.z), __fmaf_rn(wihB2, o.w, c.w));
        }
    }
    float ob = outb[0];
    bsA = __fmaf_rn(wihA2, ob, dec_b[rA]);
    bsB = __fmaf_rn(wihB2, ob, dec_b[rB]);

    float ow0 = sh_ow[lane];
    float ow1 = sh_ow[lane + 32];
    __syncthreads();

    // q = outW . hd + outb  (step-0 correction: x_0 = 0, not y(hd))
    float q = ob;
#pragma unroll 16
    for (int j = 0; j < Hn; j++) q = __fmaf_rn(sh_ow[j], hb0[j], q);

    // ---- decoder: full T steps, pure recurrence; y_{s-1} computed at step s
    //      by warp (s-1)&3 from the ring (off the critical path) ----
    float  lacc  = 0.0f;
    float* out_y = out + 1 + (size_t)Bn * Tn + (size_t)b * Tn;

    for (int s = 0; s < Tn; s++) {
        const ulonglong2* hq = (const ulonglong2*)hb4[s & 3];
        float* wout = (float*)hb4[(s + 1) & 3];

        // rotating y-projection: y_{s-1} = outW . h_s + ob
        if (s > 0 && wid == ((s - 1) & 3)) {
            const float* hr = (const float*)hb4[s & 3];
            float yp = hr[lane] * ow0 + hr[lane + 32] * ow1;
            yp += __shfl_xor_sync(0xffffffffu, yp, 16);
            yp += __shfl_xor_sync(0xffffffffu, yp, 8);
            yp += __shfl_xor_sync(0xffffffffu, yp, 4);
            yp += __shfl_xor_sync(0xffffffffu, yp, 2);
            yp += __shfl_xor_sync(0xffffffffu, yp, 1);
            if (lane == 0) {
                float y = yp + ob;
                out_y[s - 1] = y;
                if (s - 1 < seqlen) {
                    float d = xbuf[s - 1] - y;
                    lacc = __fmaf_rn(d, d, lacc);
                }
            }
        }

        unsigned long long aA0 = 0ull, aA1 = 0ull, aB0 = 0ull, aB1 = 0ull;
#pragma unroll
        for (int k = 0; k < 16; k++) {
            ulonglong2 hv = hq[k];
            ffma2(aA0, wA[2 * k],     hv.x);
            ffma2(aA1, wA[2 * k + 1], hv.y);
            ffma2(aB0, wB[2 * k],     hv.x);
            ffma2(aB1, wB[2 * k + 1], hv.y);
        }

        float sA0, sA1, sB0, sB1;
        unpack2(add2(aA0, aA1), sA0, sA1);
        unpack2(add2(aB0, aB1), sB0, sB1);
        float gA = (sA0 + sA1) + bsA;
        float gB = (sB0 + sB1) + bsB;
        if (s == 0) {                   // undo fold for x_0 = 0
            gA = __fmaf_rn(-wihA2, q, gA);
            gB = __fmaf_rn(-wihB2, q, gB);
        }

        float oA = __shfl_xor_sync(0xffffffffu, gA, 1);
        float oB = __shfl_xor_sync(0xffffffffu, gB, 1);
        float gi = even ? gA : oA;
        float gf = even ? gB : oB;
        float gg = even ? oA : gA;
        float go = even ? oB : gB;

        c_reg   = sigm(gf) * c_reg + sigm(gi) * tanh_hw(gg);
        float h = sigm(go) * tanh_hw(c_reg);
        if (even) wout[u] = h;
        __syncthreads();
    }

    // Tail: y_{T-1} from slot Tn&3 = 0, handled by warp (Tn-1)&3 = 3.
    if (wid == 3) {
        const float* hr = (const float*)hb4[Tn & 3];
        float yp = hr[lane] * ow0 + hr[lane + 32] * ow1;
        yp += __shfl_xor_sync(0xffffffffu, yp, 16);
        yp += __shfl_xor_sync(0xffffffffu, yp, 8);
        yp += __shfl_xor_sync(0xffffffffu, yp, 4);
        yp += __shfl_xor_sync(0xffffffffu, yp, 2);
        yp += __shfl_xor_sync(0xffffffffu, yp, 1);
        if (lane == 0) {
            float y = yp + ob;
            out_y[Tn - 1] = y;
            if (Tn - 1 < seqlen) {
                float d = xbuf[Tn - 1] - y;
                lacc = __fmaf_rn(d, d, lacc);
            }
        }
    }
    __syncthreads();                    // sh_s reuse below
    if (lane == 0) sh_s[wid] = lacc;    // per-warp loss partials
    __syncthreads();
    if (t == 0)
        g_partial[b] = (sh_s[0] + sh_s[1]) + (sh_s[2] + sh_s[3]);
}

// ---------- deterministic loss reduction ----------
__global__ void finalize_kernel(const int* __restrict__ seq_lengths,
                                float* __restrict__ out) {
    __shared__ double    ssum[256];
    __shared__ long long scnt[256];
    int tid = threadIdx.x;
    double    s = 0.0;
    long long c = 0;
    for (int i = tid; i < Bn; i += 256) {
        s += (double)g_partial[i];
        c += (long long)seq_lengths[i];
    }
    ssum[tid] = s;
    scnt[tid] = c;
    __syncthreads();
    for (int off = 128; off; off >>= 1) {
        if (tid < off) {
            ssum[tid] += ssum[tid + off];
            scnt[tid] += scnt[tid + off];
        }
        __syncthreads();
    }
    if (tid == 0) out[0] = (float)(ssum[0] / (double)scnt[0]);
}

extern "C" void kernel_launch(void* const* d_in, const int* in_sizes, int n_in,
                              void* d_out, int out_size) {
    const float* padded   = (const float*)d_in[0];
    const int*   seql     = (const int*)  d_in[1];
    const float* enc_Wih  = (const float*)d_in[2];
    const float* enc_Whh  = (const float*)d_in[3];
    const float* enc_b    = (const float*)d_in[4];
    const float* enc_linW = (const float*)d_in[5];
    const float* enc_linb = (const float*)d_in[6];
    const float* dec_linW = (const float*)d_in[7];
    const float* dec_linb = (const float*)d_in[8];
    const float* dec_Wih  = (const float*)d_in[9];
    const float* dec_Whh  = (const float*)d_in[10];
    const float* dec_b    = (const float*)d_in[11];
    const float* outW     = (const float*)d_in[12];
    const float* outb     = (const float*)d_in[13];
    float* out = (float*)d_out;

    // 5 launches per call, lstm first -> ncu (-s 5 -c 1) profiles lstm_kernel
    // on the first graph replay instead of the copy/finalize helpers.
    lstm_kernel<<<Bn, 128>>>(padded, seql,
                             enc_Wih, enc_Whh, enc_b,
                             enc_linW, enc_linb,
                             dec_linW, dec_linb,
                             dec_Wih, dec_Whh, dec_b,
                             outW, outb, out);

    const int n4 = (Bn * Tn) / 4;
    copy_pad_kernel<<<(n4 + 255) / 256, 256>>>((const float4*)padded, out + 1, n4);

    finalize_kernel<<<1, 256>>>(seql, out);

    nop_kernel<<<1, 1>>>();
    nop_kernel<<<1, 1>>>();
}

// round 9
// speedup vs baseline: 1.2194x; 1.2194x over previous
// R7 resubmit of the R6 fused design (R6 bench was an infra failure:
// "GB300 container failed twice" — no kernel signal). Single-change
// discipline: measure this design before touching anything else.
#include <cuda_runtime.h>

// Problem constants (fixed by the reference).
#define Bn 4096
#define Tn 2048
#define Hn 64

// Device scratch (no allocs allowed).
__device__ float        g_partial[Bn];
__device__ unsigned int g_done = 0;   // self-resets via atomicInc wrap at Bn

// ---------- packed f32x2 helpers (FFMA2 path, sm_103a) ----------
__device__ __forceinline__ unsigned long long pack2(float x, float y) {
    unsigned long long r;
    asm("mov.b64 %0, {%1, %2};" : "=l"(r) : "f"(x), "f"(y));
    return r;
}
__device__ __forceinline__ void unpack2(unsigned long long v, float& x, float& y) {
    asm("mov.b64 {%0, %1}, %2;" : "=f"(x), "=f"(y) : "l"(v));
}
__device__ __forceinline__ void ffma2(unsigned long long& d,
                                      unsigned long long a,
                                      unsigned long long b) {
    asm("fma.rn.f32x2 %0, %1, %2, %0;" : "+l"(d) : "l"(a), "l"(b));
}
__device__ __forceinline__ unsigned long long add2(unsigned long long a,
                                                   unsigned long long b) {
    unsigned long long r;
    asm("add.rn.f32x2 %0, %1, %2;" : "=l"(r) : "l"(a), "l"(b));
    return r;
}

// ---------- activations: hardware MUFU.TANH ----------
__device__ __forceinline__ float tanh_hw(float x) {
    float r;
    asm("tanh.approx.f32 %0, %1;" : "=f"(r) : "f"(x));
    return r;
}
__device__ __forceinline__ float sigm(float x) {
    return __fmaf_rn(tanh_hw(0.5f * x), 0.5f, 0.5f);
}

// ============================================================================
// Single fused kernel: one CTA (256 threads) per batch element.
// Thread t owns gate row r = (t&3)*64 + (t>>2)  (q=t&3: 0=i,1=f,2=g,3=o so the
// 4 gates of unit u sit on adjacent lanes -> shfl exchange, no 2nd barrier).
// One barrier per step; h ping-pongs between 2 SMEM slots.
// Decoder uses the rank-1 fold W' = Whh + Wih (x) outW so the y->x scalar
// feedback vanishes from the critical path; warp 0 emits y one step late.
// Loss finalize runs in the last CTA (deterministic fixed-order reduction).
// ============================================================================
__global__ __launch_bounds__(256, 2)
void lstm_kernel(const float* __restrict__ padded,
                 const int*   __restrict__ seq_lengths,
                 const float* __restrict__ enc_Wih,
                 const float* __restrict__ enc_Whh,
                 const float* __restrict__ enc_b,
                 const float* __restrict__ enc_linW,
                 const float* __restrict__ enc_linb,
                 const float* __restrict__ dec_linW,
                 const float* __restrict__ dec_linb,
                 const float* __restrict__ dec_Wih,
                 const float* __restrict__ dec_Whh,
                 const float* __restrict__ dec_b,
                 const float* __restrict__ outW,
                 const float* __restrict__ outb,
                 float* __restrict__ out) {
    __shared__ float4    hb4[2][Hn / 4];   // ping-pong hidden state
    __shared__ float4    sh_ow4[Hn / 4];   // outW (decoder fold + y proj)
    __shared__ float     xbuf[Tn];         // input sequence
    __shared__ float     sh_s[4];          // bottleneck hz
    __shared__ unsigned  s_last;           // last-block flag
    __shared__ double    red_s[256];       // loss reduction
    __shared__ long long red_c[256];

    const int b    = blockIdx.x;
    const int t    = threadIdx.x;
    const int u    = t >> 2;               // hidden unit
    const int qi   = t & 3;                // gate index 0..3
    const int row  = qi * Hn + u;          // gate row
    const int lane = t & 31;

    float* hb0   = (float*)hb4[0];
    float* sh_ow = (float*)sh_ow4;

    // Prefetch input sequence (and emit the padded copy), init state, stage outW.
    const float* xin     = padded + (size_t)b * Tn;
    float*       out_pad = out + 1 + (size_t)b * Tn;
    for (int i = t; i < Tn; i += 256) {
        float v = xin[i];
        xbuf[i] = v;
        out_pad[i] = v;
    }
    if (t < Hn) { hb0[t] = 0.0f; sh_ow[t] = outW[t]; }

    const int seqlen = seq_lengths[b];

    // Encoder weights: one row (64 floats = 32 f32x2) in registers.
    unsigned long long w[32];
    {
        const float4* wp = (const float4*)(enc_Whh + row * Hn);
#pragma unroll
        for (int k = 0; k < 16; k++) {
            float4 v = wp[k];
            w[2 * k]     = pack2(v.x, v.y);
            w[2 * k + 1] = pack2(v.z, v.w);
        }
    }
    float wih  = enc_Wih[row];
    float bias = enc_b[row];
    float c_reg = 0.0f;                    // live only on qi==0 lanes

    __syncthreads();

    // ---- encoder: state freezes at seqlen -> stop there ----
    for (int s = 0; s < seqlen; s++) {
        const ulonglong2* hq = (const ulonglong2*)hb4[s & 1];
        float* wout = (float*)hb4[(s + 1) & 1];

        unsigned long long a0 = 0ull, a1 = 0ull, a2 = 0ull, a3 = 0ull;
#pragma unroll
        for (int k = 0; k < 8; k++) {
            ulonglong2 h0 = hq[2 * k];      // broadcast LDS.128
            ulonglong2 h1 = hq[2 * k + 1];
            ffma2(a0, w[4 * k],     h0.x);
            ffma2(a1, w[4 * k + 1], h0.y);
            ffma2(a2, w[4 * k + 2], h1.x);
            ffma2(a3, w[4 * k + 3], h1.y);
        }
        float x = xbuf[s];
        float s0, s1;
        unpack2(add2(add2(a0, a1), add2(a2, a3)), s0, s1);
        float gv = (s0 + s1) + __fmaf_rn(x, wih, bias);

        // Per-gate activation (1 MUFU/thread): i,f,o -> sigm; g -> tanh.
        float arg = (qi == 2) ? gv : 0.5f * gv;
        float tv  = tanh_hw(arg);
        float a   = (qi == 2) ? tv : __fmaf_rn(tv, 0.5f, 0.5f);

        // Gather to the qi==0 lane: af=sig(f), ag=tanh(g), ao=sig(o).
        float af = __shfl_xor_sync(0xffffffffu, a, 1);
        float ag = __shfl_xor_sync(0xffffffffu, a, 2);
        float ao = __shfl_xor_sync(0xffffffffu, af, 2);
        if (qi == 0) {
            c_reg = __fmaf_rn(af, c_reg, a * ag);
            wout[u] = ao * tanh_hw(c_reg);
        }
        __syncthreads();
    }

    // ---- bottleneck: hz = sigmoid(h @ enc_linW.T + enc_linb) ----
    const float* hfin = (const float*)hb4[seqlen & 1];
    if (t < 3) {
        float s = enc_linb[t];
        const float* wl = enc_linW + t * Hn;
#pragma unroll 16
        for (int j = 0; j < Hn; j++) s = __fmaf_rn(wl[j], hfin[j], s);
        float z = sigm(s);
        sh_s[t] = z;
        out[1 + 2 * (size_t)Bn * Tn + (size_t)b * 3 + t] = z;
    }
    __syncthreads();

    // hd = hz @ dec_linW.T + dec_linb  -> slot 0 (c carries over from encoder).
    if (t < Hn) {
        hb0[t] = dec_linb[t]
               + dec_linW[t * 3 + 0] * sh_s[0]
               + dec_linW[t * 3 + 1] * sh_s[1]
               + dec_linW[t * 3 + 2] * sh_s[2];
    }

    // Decoder weights, FOLDED: W' = dec_Whh + dec_Wih (x) outW,
    // b' = dec_b + dec_Wih*outb.
    float wih2 = dec_Wih[row];
    {
        const float4* wp = (const float4*)(dec_Whh + row * Hn);
#pragma unroll
        for (int k = 0; k < 16; k++) {
            float4 v = wp[k], o = sh_ow4[k];
            w[2 * k]     = pack2(__fmaf_rn(wih2, o.x, v.x), __fmaf_rn(wih2, o.y, v.y));
            w[2 * k + 1] = pack2(__fmaf_rn(wih2, o.z, v.z), __fmaf_rn(wih2, o.w, v.w));
        }
    }
    float ob = outb[0];
    bias = __fmaf_rn(wih2, ob, dec_b[row]);

    float ow0 = sh_ow[lane];               // y-projection operands (warp 0 uses)
    float ow1 = sh_ow[lane + 32];
    __syncthreads();

    // qs = outW . hd + outb  (step-0 correction: true x_0 = 0, not y(hd)).
    float qs = ob;
#pragma unroll 16
    for (int j = 0; j < Hn; j++) qs = __fmaf_rn(sh_ow[j], hb0[j], qs);

    // ---- decoder: T steps of pure recurrence; warp 0 emits y one step late ----
    float  lacc  = 0.0f;
    float* out_y = out + 1 + (size_t)Bn * Tn + (size_t)b * Tn;

    for (int s = 0; s < Tn; s++) {
        const ulonglong2* hq = (const ulonglong2*)hb4[s & 1];
        float* wout = (float*)hb4[(s + 1) & 1];

        // y_{s-1} = outW . h_s + ob, off the critical path (warp 0 only).
        if (t < 32 && s > 0) {
            const float* hr = (const float*)hb4[s & 1];
            float yp = hr[lane] * ow0 + hr[lane + 32] * ow1;
            yp += __shfl_xor_sync(0xffffffffu, yp, 16);
            yp += __shfl_xor_sync(0xffffffffu, yp, 8);
            yp += __shfl_xor_sync(0xffffffffu, yp, 4);
            yp += __shfl_xor_sync(0xffffffffu, yp, 2);
            yp += __shfl_xor_sync(0xffffffffu, yp, 1);
            if (t == 0) {
                float y = yp + ob;
                out_y[s - 1] = y;
                if (s - 1 < seqlen) {
                    float d = xbuf[s - 1] - y;
                    lacc = __fmaf_rn(d, d, lacc);
                }
            }
        }

        unsigned long long a0 = 0ull, a1 = 0ull, a2 = 0ull, a3 = 0ull;
#pragma unroll
        for (int k = 0; k < 8; k++) {
            ulonglong2 h0 = hq[2 * k];
            ulonglong2 h1 = hq[2 * k + 1];
            ffma2(a0, w[4 * k],     h0.x);
            ffma2(a1, w[4 * k + 1], h0.y);
            ffma2(a2, w[4 * k + 2], h1.x);
            ffma2(a3, w[4 * k + 3], h1.y);
        }
        float s0, s1;
        unpack2(add2(add2(a0, a1), add2(a2, a3)), s0, s1);
        float gv = (s0 + s1) + bias;
        if (s == 0) gv = __fmaf_rn(-wih2, qs, gv);   // undo fold: x_0 = 0

        float arg = (qi == 2) ? gv : 0.5f * gv;
        float tv  = tanh_hw(arg);
        float a   = (qi == 2) ? tv : __fmaf_rn(tv, 0.5f, 0.5f);

        float af = __shfl_xor_sync(0xffffffffu, a, 1);
        float ag = __shfl_xor_sync(0xffffffffu, a, 2);
        float ao = __shfl_xor_sync(0xffffffffu, af, 2);
        if (qi == 0) {
            c_reg = __fmaf_rn(af, c_reg, a * ag);
            wout[u] = ao * tanh_hw(c_reg);
        }
        __syncthreads();
    }

    // Tail: y_{T-1} from slot Tn&1 = 0.
    if (t < 32) {
        const float* hr = (const float*)hb4[Tn & 1];
        float yp = hr[lane] * ow0 + hr[lane + 32] * ow1;
        yp += __shfl_xor_sync(0xffffffffu, yp, 16);
        yp += __shfl_xor_sync(0xffffffffu, yp, 8);
        yp += __shfl_xor_sync(0xffffffffu, yp, 4);
        yp += __shfl_xor_sync(0xffffffffu, yp, 2);
        yp += __shfl_xor_sync(0xffffffffu, yp, 1);
        if (t == 0) {
            float y = yp + ob;
            out_y[Tn - 1] = y;
            if (Tn - 1 < seqlen) {
                float d = xbuf[Tn - 1] - y;
                lacc = __fmaf_rn(d, d, lacc);
            }
            g_partial[b] = lacc;
        }
    }

    // ---- last-block deterministic loss finalize ----
    __threadfence();
    if (t == 0) s_last = atomicInc(&g_done, Bn - 1);  // wraps to 0 each run
    __syncthreads();
    if (s_last == Bn - 1) {
        __threadfence();
        double    s = 0.0;
        long long c = 0;
        for (int i = t; i < Bn; i += 256) {           // fixed order
            s += (double)g_partial[i];
            c += (long long)seq_lengths[i];
        }
        red_s[t] = s;
        red_c[t] = c;
        __syncthreads();
        for (int off = 128; off; off >>= 1) {         // fixed tree
            if (t < off) {
                red_s[t] += red_s[t + off];
                red_c[t] += red_c[t + off];
            }
            __syncthreads();
        }
        if (t == 0) out[0] = (float)(red_s[0] / (double)red_c[0]);
    }
}

extern "C" void kernel_launch(void* const* d_in, const int* in_sizes, int n_in,
                              void* d_out, int out_size) {
    const float* padded   = (const float*)d_in[0];
    const int*   seql     = (const int*)  d_in[1];
    const float* enc_Wih  = (const float*)d_in[2];
    const float* enc_Whh  = (const float*)d_in[3];
    const float* enc_b    = (const float*)d_in[4];
    const float* enc_linW = (const float*)d_in[5];
    const float* enc_linb = (const float*)d_in[6];
    const float* dec_linW = (const float*)d_in[7];
    const float* dec_linb = (const float*)d_in[8];
    const float* dec_Wih  = (const float*)d_in[9];
    const float* dec_Whh  = (const float*)d_in[10];
    const float* dec_b    = (const float*)d_in[11];
    const float* outW     = (const float*)d_in[12];
    const float* outb     = (const float*)d_in[13];
    float* out = (float*)d_out;

    // Single kernel: [loss(1) | padded(B*T) | output(B*T) | hz(B*3)] all here.
    lstm_kernel<<<Bn, 256>>>(padded, seql,
                             enc_Wih, enc_Whh, enc_b,
                             enc_linW, enc_linb,
                             dec_linW, dec_linb,
                             dec_Wih, dec_Whh, dec_b,
                             outW, outb, out);
}

// round 10
// speedup vs baseline: 1.6945x; 1.3895x over previous
// R4-structure (measured best, 15.86ms) + MUFU.TANH activations + single-
// kernel fusion (pad copy + last-block loss). One structural delta vs the
// measured best: activations. Fusion shell validated in R9.
#include <cuda_runtime.h>

#define Bn 4096
#define Tn 2048
#define Hn 64

// Device scratch (no allocs allowed).
__device__ float        g_partial[Bn];
__device__ unsigned int g_done = 0;   // self-resets via atomicInc wrap at Bn

// ---------- packed f32x2 helpers (FFMA2 path, sm_103a) ----------
__device__ __forceinline__ unsigned long long pack2(float x, float y) {
    unsigned long long r;
    asm("mov.b64 %0, {%1, %2};" : "=l"(r) : "f"(x), "f"(y));
    return r;
}
__device__ __forceinline__ void unpack2(unsigned long long v, float& x, float& y) {
    asm("mov.b64 {%0, %1}, %2;" : "=f"(x), "=f"(y) : "l"(v));
}
__device__ __forceinline__ void ffma2(unsigned long long& d,
                                      unsigned long long a,
                                      unsigned long long b) {
    asm("fma.rn.f32x2 %0, %1, %2, %0;" : "+l"(d) : "l"(a), "l"(b));
}
__device__ __forceinline__ unsigned long long add2(unsigned long long a,
                                                   unsigned long long b) {
    unsigned long long r;
    asm("add.rn.f32x2 %0, %1, %2;" : "=l"(r) : "l"(a), "l"(b));
    return r;
}

// ---------- activations: hardware MUFU.TANH ----------
__device__ __forceinline__ float tanh_hw(float x) {
    float r;
    asm("tanh.approx.f32 %0, %1;" : "=f"(r) : "f"(x));
    return r;
}
__device__ __forceinline__ float sigm(float x) {
    return __fmaf_rn(tanh_hw(0.5f * x), 0.5f, 0.5f);
}

// ============================================================================
// One CTA (128 threads) per batch element.
// Thread pair (2u, 2u+1) owns hidden unit u:
//   even thread: gate rows (u, 64+u)      = (i, f)
//   odd  thread: gate rows (128+u, 192+u) = (g, o)
// Gate exchange = one depth-1 shfl_xor(1) pair; activations computed
// redundantly in the pair (no extra serialization). One barrier per step,
// h ping-pongs between 2 SMEM slots. Decoder uses the rank-1 fold
// W' = Whh + Wih (x) outW so y->x feedback leaves the critical path; warp 0
// emits y one step late. Loss finalize runs in the last CTA.
// ============================================================================
__global__ __launch_bounds__(128, 3)
void lstm_kernel(const float* __restrict__ padded,
                 const int*   __restrict__ seq_lengths,
                 const float* __restrict__ enc_Wih,
                 const float* __restrict__ enc_Whh,
                 const float* __restrict__ enc_b,
                 const float* __restrict__ enc_linW,
                 const float* __restrict__ enc_linb,
                 const float* __restrict__ dec_linW,
                 const float* __restrict__ dec_linb,
                 const float* __restrict__ dec_Wih,
                 const float* __restrict__ dec_Whh,
                 const float* __restrict__ dec_b,
                 const float* __restrict__ outW,
                 const float* __restrict__ outb,
                 float* __restrict__ out) {
    __shared__ float4    hb4[2][Hn / 4];   // ping-pong hidden state
    __shared__ float4    sh_ow4[Hn / 4];   // outW (decoder fold + y proj)
    __shared__ float     xbuf[Tn];         // input sequence
    __shared__ float     sh_s[4];          // bottleneck hz
    __shared__ unsigned  s_last;           // last-block flag
    __shared__ double    red_s[128];       // loss reduction
    __shared__ long long red_c[128];

    const int  b    = blockIdx.x;
    const int  t    = threadIdx.x;
    const int  u    = t >> 1;
    const bool even = !(t & 1);
    const int  lane = t & 31;

    float* hb0   = (float*)hb4[0];
    float* sh_ow = (float*)sh_ow4;

    const int rA = even ? u      : 128 + u;
    const int rB = even ? 64 + u : 192 + u;

    // Prefetch input sequence (and emit the padded copy), init state, stage outW.
    const float* xin     = padded + (size_t)b * Tn;
    float*       out_pad = out + 1 + (size_t)b * Tn;
    for (int i = t; i < Tn; i += 128) {
        float v = xin[i];
        xbuf[i] = v;
        out_pad[i] = v;
    }
    if (t < Hn) { hb0[t] = 0.0f; sh_ow[t] = outW[t]; }

    const int seqlen = seq_lengths[b];

    // Encoder weights -> registers (2 rows x 64 = 64 f32x2 pairs).
    unsigned long long wA[32], wB[32];
    {
        const float4* pA = (const float4*)(enc_Whh + rA * Hn);
        const float4* pB = (const float4*)(enc_Whh + rB * Hn);
#pragma unroll
        for (int k = 0; k < 16; k++) {
            float4 a = pA[k];
            wA[2 * k]     = pack2(a.x, a.y);
            wA[2 * k + 1] = pack2(a.z, a.w);
            float4 c = pB[k];
            wB[2 * k]     = pack2(c.x, c.y);
            wB[2 * k + 1] = pack2(c.z, c.w);
        }
    }
    float wihA = enc_Wih[rA], wihB = enc_Wih[rB];
    float bsA  = enc_b[rA],   bsB  = enc_b[rB];
    float c_reg = 0.0f;                 // cell state (replicated in pair)

    __syncthreads();

    // ---- encoder: state freezes at seqlen -> stop there ----
    for (int s = 0; s < seqlen; s++) {
        const ulonglong2* hq = (const ulonglong2*)hb4[s & 1];
        float* wout = (float*)hb4[(s + 1) & 1];

        unsigned long long aA0 = 0ull, aA1 = 0ull, aB0 = 0ull, aB1 = 0ull;
#pragma unroll
        for (int k = 0; k < 16; k++) {
            ulonglong2 hv = hq[k];      // broadcast LDS.128
            ffma2(aA0, wA[2 * k],     hv.x);
            ffma2(aA1, wA[2 * k + 1], hv.y);
            ffma2(aB0, wB[2 * k],     hv.x);
            ffma2(aB1, wB[2 * k + 1], hv.y);
        }
        float x = xbuf[s];
        float sA0, sA1, sB0, sB1;
        unpack2(add2(aA0, aA1), sA0, sA1);
        unpack2(add2(aB0, aB1), sB0, sB1);
        float gA = (sA0 + sA1) + __fmaf_rn(x, wihA, bsA);
        float gB = (sB0 + sB1) + __fmaf_rn(x, wihB, bsB);

        float oA = __shfl_xor_sync(0xffffffffu, gA, 1);   // depth-1 exchange
        float oB = __shfl_xor_sync(0xffffffffu, gB, 1);
        float gi = even ? gA : oA;
        float gf = even ? gB : oB;
        float gg = even ? oA : gA;
        float go = even ? oB : gB;

        c_reg   = sigm(gf) * c_reg + sigm(gi) * tanh_hw(gg);
        float h = sigm(go) * tanh_hw(c_reg);
        if (even) wout[u] = h;
        __syncthreads();
    }

    // ---- bottleneck: hz = sigmoid(h @ enc_linW.T + enc_linb) ----
    const float* hfin = (const float*)hb4[seqlen & 1];
    if (t < 3) {
        float s = enc_linb[t];
        const float* wl = enc_linW + t * Hn;
#pragma unroll 16
        for (int j = 0; j < Hn; j++) s = __fmaf_rn(wl[j], hfin[j], s);
        float z = sigm(s);
        sh_s[t] = z;
        out[1 + 2 * (size_t)Bn * Tn + (size_t)b * 3 + t] = z;
    }
    __syncthreads();

    // hd = hz @ dec_linW.T + dec_linb  (into slot 0; c carries over)
    float z0 = sh_s[0], z1 = sh_s[1], z2 = sh_s[2];
    __syncthreads();                    // hfin reads done before overwrite
    if (t < Hn) {
        hb0[t] = dec_linb[t]
               + dec_linW[t * 3 + 0] * z0
               + dec_linW[t * 3 + 1] * z1
               + dec_linW[t * 3 + 2] * z2;
    }

    // Decoder weights, FOLDED: W' = dec_Whh + dec_Wih (x) outW,
    // b' = dec_b + dec_Wih*outb.  Removes y->x from the critical path.
    float wihA2 = dec_Wih[rA], wihB2 = dec_Wih[rB];
    {
        const float4* pA = (const float4*)(dec_Whh + rA * Hn);
        const float4* pB = (const float4*)(dec_Whh + rB * Hn);
#pragma unroll
        for (int k = 0; k < 16; k++) {
            float4 a = pA[k], c = pB[k], o = sh_ow4[k];
            wA[2 * k]     = pack2(__fmaf_rn(wihA2, o.x, a.x), __fmaf_rn(wihA2, o.y, a.y));
            wA[2 * k + 1] = pack2(__fmaf_rn(wihA2, o.z, a.z), __fmaf_rn(wihA2, o.w, a.w));
            wB[2 * k]     = pack2(__fmaf_rn(wihB2, o.x, c.x), __fmaf_rn(wihB2, o.y, c.y));
            wB[2 * k + 1] = pack2(__fmaf_rn(wihB2, o.z, c.z), __fmaf_rn(wihB2, o.w, c.w));
        }
    }
    float ob = outb[0];
    bsA = __fmaf_rn(wihA2, ob, dec_b[rA]);
    bsB = __fmaf_rn(wihB2, ob, dec_b[rB]);

    float ow0 = sh_ow[lane];            // y-projection operands (warp 0 uses)
    float ow1 = sh_ow[lane + 32];
    __syncthreads();

    // qs = outW . hd + outb  (step-0 correction: true x_0 = 0, not y(hd))
    float qs = ob;
#pragma unroll 16
    for (int j = 0; j < Hn; j++) qs = __fmaf_rn(sh_ow[j], hb0[j], qs);

    // ---- decoder: T steps of pure recurrence; warp 0 emits y one step late ----
    float  lacc  = 0.0f;
    float* out_y = out + 1 + (size_t)Bn * Tn + (size_t)b * Tn;

    for (int s = 0; s < Tn; s++) {
        const ulonglong2* hq = (const ulonglong2*)hb4[s & 1];
        float* wout = (float*)hb4[(s + 1) & 1];

        // y_{s-1} = outW . h_s + ob, off the critical path (warp 0 only).
        if (t < 32 && s > 0) {
            const float* hr = (const float*)hb4[s & 1];
            float yp = hr[lane] * ow0 + hr[lane + 32] * ow1;
            yp += __shfl_xor_sync(0xffffffffu, yp, 16);
            yp += __shfl_xor_sync(0xffffffffu, yp, 8);
            yp += __shfl_xor_sync(0xffffffffu, yp, 4);
            yp += __shfl_xor_sync(0xffffffffu, yp, 2);
            yp += __shfl_xor_sync(0xffffffffu, yp, 1);
            if (t == 0) {
                float y = yp + ob;
                out_y[s - 1] = y;
                if (s - 1 < seqlen) {
                    float d = xbuf[s - 1] - y;
                    lacc = __fmaf_rn(d, d, lacc);
                }
            }
        }

        unsigned long long aA0 = 0ull, aA1 = 0ull, aB0 = 0ull, aB1 = 0ull;
#pragma unroll
        for (int k = 0; k < 16; k++) {
            ulonglong2 hv = hq[k];
            ffma2(aA0, wA[2 * k],     hv.x);
            ffma2(aA1, wA[2 * k + 1], hv.y);
            ffma2(aB0, wB[2 * k],     hv.x);
            ffma2(aB1, wB[2 * k + 1], hv.y);
        }

        float sA0, sA1, sB0, sB1;
        unpack2(add2(aA0, aA1), sA0, sA1);
        unpack2(add2(aB0, aB1), sB0, sB1);
        float gA = (sA0 + sA1) + bsA;
        float gB = (sB0 + sB1) + bsB;
        if (s == 0) {                   // undo fold: x_0 = 0
            gA = __fmaf_rn(-wihA2, qs, gA);
            gB = __fmaf_rn(-wihB2, qs, gB);
        }

        float oA = __shfl_xor_sync(0xffffffffu, gA, 1);
        float oB = __shfl_xor_sync(0xffffffffu, gB, 1);
        float gi = even ? gA : oA;
        float gf = even ? gB : oB;
        float gg = even ? oA : gA;
        float go = even ? oB : gB;

        c_reg   = sigm(gf) * c_reg + sigm(gi) * tanh_hw(gg);
        float h = sigm(go) * tanh_hw(c_reg);
        if (even) wout[u] = h;
        __syncthreads();
    }

    // Tail: y_{T-1} from slot Tn&1 = 0.
    if (t < 32) {
        const float* hr = (const float*)hb4[Tn & 1];
        float yp = hr[lane] * ow0 + hr[lane + 32] * ow1;
        yp += __shfl_xor_sync(0xffffffffu, yp, 16);
        yp += __shfl_xor_sync(0xffffffffu, yp, 8);
        yp += __shfl_xor_sync(0xffffffffu, yp, 4);
        yp += __shfl_xor_sync(0xffffffffu, yp, 2);
        yp += __shfl_xor_sync(0xffffffffu, yp, 1);
        if (t == 0) {
            float y = yp + ob;
            out_y[Tn - 1] = y;
            if (Tn - 1 < seqlen) {
                float d = xbuf[Tn - 1] - y;
                lacc = __fmaf_rn(d, d, lacc);
            }
            g_partial[b] = lacc;
        }
    }

    // ---- last-block deterministic loss finalize ----
    __threadfence();
    if (t == 0) s_last = atomicInc(&g_done, Bn - 1);  // wraps to 0 each run
    __syncthreads();
    if (s_last == Bn - 1) {
        __threadfence();
        double    s = 0.0;
        long long c = 0;
        for (int i = t; i < Bn; i += 128) {           // fixed order
            s += (double)g_partial[i];
            c += (long long)seq_lengths[i];
        }
        red_s[t] = s;
        red_c[t] = c;
        __syncthreads();
        for (int off = 64; off; off >>= 1) {          // fixed tree
            if (t < off) {
                red_s[t] += red_s[t + off];
                red_c[t] += red_c[t + off];
            }
            __syncthreads();
        }
        if (t == 0) out[0] = (float)(red_s[0] / (double)red_c[0]);
    }
}

extern "C" void kernel_launch(void* const* d_in, const int* in_sizes, int n_in,
                              void* d_out, int out_size) {
    const float* padded   = (const float*)d_in[0];
    const int*   seql     = (const int*)  d_in[1];
    const float* enc_Wih  = (const float*)d_in[2];
    const float* enc_Whh  = (const float*)d_in[3];
    const float* enc_b    = (const float*)d_in[4];
    const float* enc_linW = (const float*)d_in[5];
    const float* enc_linb = (const float*)d_in[6];
    const float* dec_linW = (const float*)d_in[7];
    const float* dec_linb = (const float*)d_in[8];
    const float* dec_Wih  = (const float*)d_in[9];
    const float* dec_Whh  = (const float*)d_in[10];
    const float* dec_b    = (const float*)d_in[11];
    const float* outW     = (const float*)d_in[12];
    const float* outb     = (const float*)d_in[13];
    float* out = (float*)d_out;

    // Single kernel: [loss(1) | padded(B*T) | output(B*T) | hz(B*3)] all here.
    lstm_kernel<<<Bn, 128>>>(padded, seql,
                             enc_Wih, enc_Whh, enc_b,
                             enc_linW, enc_linb,
                             dec_linW, dec_linb,
                             dec_Wih, dec_Whh, dec_b,
                             outW, outb, out);
}

// round 11
// speedup vs baseline: 1.7223x; 1.0164x over previous
// R10 (12.89ms, measured best) + 2 batch elements per CTA sharing the same
// register-resident weights (weights are batch-invariant!), + seqlen counting
// sort so paired elements have near-equal encoder lengths and long jobs go
// first. Tail (shfl/MUFU/BAR) now amortizes over 2 recurrences per warp.
#include <cuda_runtime.h>

#define Bn 4096
#define Tn 2048
#define Hn 64
#define NCTA (Bn / 2)

// Device scratch (no allocs allowed).
__device__ float        g_partial[Bn];
__device__ int          g_perm[Bn];
__device__ unsigned int g_done = 0;   // self-resets via atomicInc wrap at NCTA

// ---------- packed f32x2 helpers (FFMA2 path, sm_103a) ----------
__device__ __forceinline__ unsigned long long pack2(float x, float y) {
    unsigned long long r;
    asm("mov.b64 %0, {%1, %2};" : "=l"(r) : "f"(x), "f"(y));
    return r;
}
__device__ __forceinline__ void unpack2(unsigned long long v, float& x, float& y) {
    asm("mov.b64 {%0, %1}, %2;" : "=f"(x), "=f"(y) : "l"(v));
}
__device__ __forceinline__ void ffma2(unsigned long long& d,
                                      unsigned long long a,
                                      unsigned long long b) {
    asm("fma.rn.f32x2 %0, %1, %2, %0;" : "+l"(d) : "l"(a), "l"(b));
}
__device__ __forceinline__ unsigned long long add2(unsigned long long a,
                                                   unsigned long long b) {
    unsigned long long r;
    asm("add.rn.f32x2 %0, %1, %2;" : "=l"(r) : "l"(a), "l"(b));
    return r;
}

// ---------- activations: hardware MUFU.TANH ----------
__device__ __forceinline__ float tanh_hw(float x) {
    float r;
    asm("tanh.approx.f32 %0, %1;" : "=f"(r) : "f"(x));
    return r;
}
__device__ __forceinline__ float sigm(float x) {
    return __fmaf_rn(tanh_hw(0.5f * x), 0.5f, 0.5f);
}

// ---------- seqlen counting sort (descending) -> g_perm ----------
// Output is invariant to intra-bucket order (batch elements are independent),
// so atomic nondeterminism here cannot change d_out.
__global__ void sort_kernel(const int* __restrict__ seql) {
    __shared__ int off[2049];
    int t = threadIdx.x;
    for (int i = t; i < 2049; i += 1024) off[i] = 0;
    __syncthreads();
    for (int i = t; i < Bn; i += 1024) atomicAdd(&off[seql[i]], 1);
    __syncthreads();
    if (t == 0) {                        // descending prefix (2049 iters, once)
        int acc = 0;
        for (int v = 2048; v >= 1; v--) { int h = off[v]; off[v] = acc; acc += h; }
    }
    __syncthreads();
    for (int i = t; i < Bn; i += 1024) {
        int p = atomicAdd(&off[seql[i]], 1);
        g_perm[p] = i;
    }
}

// ============================================================================
// One CTA (128 threads) per PAIR of batch elements (sorted-adjacent lengths).
// Thread pair (2u, 2u+1) owns hidden unit u; even thread computes gate rows
// (u, 64+u) = (i,f), odd (128+u, 192+u) = (g,o). Weights register-resident,
// SHARED by both batch recurrences. One barrier per step-pair. Gate exchange
// = depth-1 shfl_xor(1). Decoder rank-1 fold kills the y->x feedback; warps
// 0/1 emit y for b0/b1 one step late. Last CTA finalizes the loss.
// ============================================================================
__global__ __launch_bounds__(128, 2)
void lstm_kernel(const float* __restrict__ padded,
                 const int*   __restrict__ seq_lengths,
                 const float* __restrict__ enc_Wih,
                 const float* __restrict__ enc_Whh,
                 const float* __restrict__ enc_b,
                 const float* __restrict__ enc_linW,
                 const float* __restrict__ enc_linb,
                 const float* __restrict__ dec_linW,
                 const float* __restrict__ dec_linb,
                 const float* __restrict__ dec_Wih,
                 const float* __restrict__ dec_Whh,
                 const float* __restrict__ dec_b,
                 const float* __restrict__ outW,
                 const float* __restrict__ outb,
                 float* __restrict__ out) {
    __shared__ float4    hb4[2][2][Hn / 4];  // [batch][slot] ping-pong h
    __shared__ float4    sh_ow4[Hn / 4];     // outW
    __shared__ float     xbuf[2][Tn];        // both input sequences
    __shared__ float     sh_hz[2][4];        // bottleneck hz per batch
    __shared__ unsigned  s_last;
    __shared__ double    red_s[128];
    __shared__ long long red_c[128];

    const int  t    = threadIdx.x;
    const int  u    = t >> 1;
    const bool even = !(t & 1);
    const int  lane = t & 31;
    const int  wid  = t >> 5;

    float* sh_ow = (float*)sh_ow4;

    const int rA = even ? u      : 128 + u;
    const int rB = even ? 64 + u : 192 + u;

    const int b0 = g_perm[2 * blockIdx.x];
    const int b1 = g_perm[2 * blockIdx.x + 1];

    // Prefetch both input sequences (and emit padded copies), init state.
    const float* xin0 = padded + (size_t)b0 * Tn;
    const float* xin1 = padded + (size_t)b1 * Tn;
    float* op0 = out + 1 + (size_t)b0 * Tn;
    float* op1 = out + 1 + (size_t)b1 * Tn;
    for (int i = t; i < Tn; i += 128) {
        float v0 = xin0[i], v1 = xin1[i];
        xbuf[0][i] = v0; op0[i] = v0;
        xbuf[1][i] = v1; op1[i] = v1;
    }
    if (t < Hn) {
        ((float*)hb4[0][0])[t] = 0.0f;
        ((float*)hb4[1][0])[t] = 0.0f;
        sh_ow[t] = outW[t];
    }
    const int sl0 = seq_lengths[b0];
    const int sl1 = seq_lengths[b1];
    const int smax = max(sl0, sl1);

    // Encoder weights (shared by both recurrences): 2 rows x 64 in registers.
    unsigned long long wA[32], wB[32];
    {
        const float4* pA = (const float4*)(enc_Whh + rA * Hn);
        const float4* pB = (const float4*)(enc_Whh + rB * Hn);
#pragma unroll
        for (int k = 0; k < 16; k++) {
            float4 a = pA[k];
            wA[2 * k]     = pack2(a.x, a.y);
            wA[2 * k + 1] = pack2(a.z, a.w);
            float4 c = pB[k];
            wB[2 * k]     = pack2(c.x, c.y);
            wB[2 * k + 1] = pack2(c.z, c.w);
        }
    }
    float wihA = enc_Wih[rA], wihB = enc_Wih[rB];
    float bsA  = enc_b[rA],   bsB  = enc_b[rB];
    float c0 = 0.0f, c1 = 0.0f;     // cell states (replicated in pair)
    float hc0 = 0.0f, hc1 = 0.0f;   // current h of unit u (freeze-forwarding)

    __syncthreads();

    // ---- encoder: run to max(sl0,sl1); per-batch state freeze ----
    for (int s = 0; s < smax; s++) {
        const ulonglong2* hq0 = (const ulonglong2*)hb4[0][s & 1];
        const ulonglong2* hq1 = (const ulonglong2*)hb4[1][s & 1];
        float* wo0 = (float*)hb4[0][(s + 1) & 1];
        float* wo1 = (float*)hb4[1][(s + 1) & 1];

        unsigned long long a00 = 0ull, a01 = 0ull, a02 = 0ull, a03 = 0ull;
        unsigned long long a10 = 0ull, a11 = 0ull, a12 = 0ull, a13 = 0ull;
#pragma unroll
        for (int k = 0; k < 16; k++) {
            ulonglong2 h0 = hq0[k];     // broadcast LDS.128
            ulonglong2 h1 = hq1[k];
            ffma2(a00, wA[2 * k],     h0.x);
            ffma2(a01, wA[2 * k + 1], h0.y);
            ffma2(a02, wB[2 * k],     h0.x);
            ffma2(a03, wB[2 * k + 1], h0.y);
            ffma2(a10, wA[2 * k],     h1.x);
            ffma2(a11, wA[2 * k + 1], h1.y);
            ffma2(a12, wB[2 * k],     h1.x);
            ffma2(a13, wB[2 * k + 1], h1.y);
        }
        float x0 = xbuf[0][s], x1 = xbuf[1][s];

        // ---- batch 0 tail ----
        {
            float sA0, sA1, sB0, sB1;
            unpack2(add2(a00, a01), sA0, sA1);
            unpack2(add2(a02, a03), sB0, sB1);
            float gA = (sA0 + sA1) + __fmaf_rn(x0, wihA, bsA);
            float gB = (sB0 + sB1) + __fmaf_rn(x0, wihB, bsB);
            float oA = __shfl_xor_sync(0xffffffffu, gA, 1);
            float oB = __shfl_xor_sync(0xffffffffu, gB, 1);
            float gi = even ? gA : oA;
            float gf = even ? gB : oB;
            float gg = even ? oA : gA;
            float go = even ? oB : gB;
            if (s < sl0) {
                c0  = sigm(gf) * c0 + sigm(gi) * tanh_hw(gg);
                hc0 = sigm(go) * tanh_hw(c0);
            }
            if (even) wo0[u] = hc0;
        }
        // ---- batch 1 tail ----
        {
            float sA0, sA1, sB0, sB1;
            unpack2(add2(a10, a11), sA0, sA1);
            unpack2(add2(a12, a13), sB0, sB1);
            float gA = (sA0 + sA1) + __fmaf_rn(x1, wihA, bsA);
            float gB = (sB0 + sB1) + __fmaf_rn(x1, wihB, bsB);
            float oA = __shfl_xor_sync(0xffffffffu, gA, 1);
            float oB = __shfl_xor_sync(0xffffffffu, gB, 1);
            float gi = even ? gA : oA;
            float gf = even ? gB : oB;
            float gg = even ? oA : gA;
            float go = even ? oB : gB;
            if (s < sl1) {
                c1  = sigm(gf) * c1 + sigm(gi) * tanh_hw(gg);
                hc1 = sigm(go) * tanh_hw(c1);
            }
            if (even) wo1[u] = hc1;
        }
        __syncthreads();
    }

    // ---- bottleneck per batch (warp 0 does b0, warp 1 does b1) ----
    // Freeze-forwarding keeps slot smax&1 correct for BOTH batches.
    {
        const float* hf0 = (const float*)hb4[0][smax & 1];
        const float* hf1 = (const float*)hb4[1][smax & 1];
        if (t < 3) {
            float s = enc_linb[t];
            const float* wl = enc_linW + t * Hn;
#pragma unroll 16
            for (int j = 0; j < Hn; j++) s = __fmaf_rn(wl[j], hf0[j], s);
            float z = sigm(s);
            sh_hz[0][t] = z;
            out[1 + 2 * (size_t)Bn * Tn + (size_t)b0 * 3 + t] = z;
        } else if (t >= 32 && t < 35) {
            int r = t - 32;
            float s = enc_linb[r];
            const float* wl = enc_linW + r * Hn;
#pragma unroll 16
            for (int j = 0; j < Hn; j++) s = __fmaf_rn(wl[j], hf1[j], s);
            float z = sigm(s);
            sh_hz[1][r] = z;
            out[1 + 2 * (size_t)Bn * Tn + (size_t)b1 * 3 + r] = z;
        }
    }
    __syncthreads();

    // hd -> slot 0 of each batch (c carries over from encoder).
    if (t < Hn) {
        ((float*)hb4[0][0])[t] = dec_linb[t]
            + dec_linW[t * 3 + 0] * sh_hz[0][0]
            + dec_linW[t * 3 + 1] * sh_hz[0][1]
            + dec_linW[t * 3 + 2] * sh_hz[0][2];
        ((float*)hb4[1][0])[t] = dec_linb[t]
            + dec_linW[t * 3 + 0] * sh_hz[1][0]
            + dec_linW[t * 3 + 1] * sh_hz[1][1]
            + dec_linW[t * 3 + 2] * sh_hz[1][2];
    }

    // Decoder weights, FOLDED: W' = dec_Whh + dec_Wih (x) outW,
    // b' = dec_b + dec_Wih*outb (shared by both batches).
    float wihA2 = dec_Wih[rA], wihB2 = dec_Wih[rB];
    {
        const float4* pA = (const float4*)(dec_Whh + rA * Hn);
        const float4* pB = (const float4*)(dec_Whh + rB * Hn);
#pragma unroll
        for (int k = 0; k < 16; k++) {
            float4 a = pA[k], c = pB[k], o = sh_ow4[k];
            wA[2 * k]     = pack2(__fmaf_rn(wihA2, o.x, a.x), __fmaf_rn(wihA2, o.y, a.y));
            wA[2 * k + 1] = pack2(__fmaf_rn(wihA2, o.z, a.z), __fmaf_rn(wihA2, o.w, a.w));
            wB[2 * k]     = pack2(__fmaf_rn(wihB2, o.x, c.x), __fmaf_rn(wihB2, o.y, c.y));
            wB[2 * k + 1] = pack2(__fmaf_rn(wihB2, o.z, c.z), __fmaf_rn(wihB2, o.w, c.w));
        }
    }
    float ob = outb[0];
    bsA = __fmaf_rn(wihA2, ob, dec_b[rA]);
    bsB = __fmaf_rn(wihB2, ob, dec_b[rB]);

    float ow0 = sh_ow[lane];
    float ow1 = sh_ow[lane + 32];
    __syncthreads();

    // qs_j = outW . hd_j + outb (step-0 correction: true x_0 = 0).
    float qs0 = ob, qs1 = ob;
    {
        const float* hd0 = (const float*)hb4[0][0];
        const float* hd1 = (const float*)hb4[1][0];
#pragma unroll 16
        for (int j = 0; j < Hn; j++) {
            qs0 = __fmaf_rn(sh_ow[j], hd0[j], qs0);
            qs1 = __fmaf_rn(sh_ow[j], hd1[j], qs1);
        }
    }

    // ---- decoder: T steps, both recurrences; warps 0/1 emit y one step late ----
    float  lacc  = 0.0f;                 // t==0 holds b0's, t==32 holds b1's
    float* oy0 = out + 1 + (size_t)Bn * Tn + (size_t)b0 * Tn;
    float* oy1 = out + 1 + (size_t)Bn * Tn + (size_t)b1 * Tn;

    for (int s = 0; s < Tn; s++) {
        const ulonglong2* hq0 = (const ulonglong2*)hb4[0][s & 1];
        const ulonglong2* hq1 = (const ulonglong2*)hb4[1][s & 1];
        float* wo0 = (float*)hb4[0][(s + 1) & 1];
        float* wo1 = (float*)hb4[1][(s + 1) & 1];

        // y_{s-1}: warp 0 -> b0, warp 1 -> b1 (off the critical path).
        if (s > 0 && wid < 2) {
            const float* hr = (const float*)hb4[wid][s & 1];
            float yp = hr[lane] * ow0 + hr[lane + 32] * ow1;
            yp += __shfl_xor_sync(0xffffffffu, yp, 16);
            yp += __shfl_xor_sync(0xffffffffu, yp, 8);
            yp += __shfl_xor_sync(0xffffffffu, yp, 4);
            yp += __shfl_xor_sync(0xffffffffu, yp, 2);
            yp += __shfl_xor_sync(0xffffffffu, yp, 1);
            if (lane == 0) {
                float y = yp + ob;
                if (wid == 0) {
                    oy0[s - 1] = y;
                    if (s - 1 < sl0) { float d = xbuf[0][s - 1] - y; lacc = __fmaf_rn(d, d, lacc); }
                } else {
                    oy1[s - 1] = y;
                    if (s - 1 < sl1) { float d = xbuf[1][s - 1] - y; lacc = __fmaf_rn(d, d, lacc); }
                }
            }
        }

        unsigned long long a00 = 0ull, a01 = 0ull, a02 = 0ull, a03 = 0ull;
        unsigned long long a10 = 0ull, a11 = 0ull, a12 = 0ull, a13 = 0ull;
#pragma unroll
        for (int k = 0; k < 16; k++) {
            ulonglong2 h0 = hq0[k];
            ulonglong2 h1 = hq1[k];
            ffma2(a00, wA[2 * k],     h0.x);
            ffma2(a01, wA[2 * k + 1], h0.y);
            ffma2(a02, wB[2 * k],     h0.x);
            ffma2(a03, wB[2 * k + 1], h0.y);
            ffma2(a10, wA[2 * k],     h1.x);
            ffma2(a11, wA[2 * k + 1], h1.y);
            ffma2(a12, wB[2 * k],     h1.x);
            ffma2(a13, wB[2 * k + 1], h1.y);
        }

        // ---- batch 0 tail ----
        {
            float sA0, sA1, sB0, sB1;
            unpack2(add2(a00, a01), sA0, sA1);
            unpack2(add2(a02, a03), sB0, sB1);
            float gA = (sA0 + sA1) + bsA;
            float gB = (sB0 + sB1) + bsB;
            if (s == 0) {
                gA = __fmaf_rn(-wihA2, qs0, gA);
                gB = __fmaf_rn(-wihB2, qs0, gB);
            }
            float oA = __shfl_xor_sync(0xffffffffu, gA, 1);
            float oB = __shfl_xor_sync(0xffffffffu, gB, 1);
            float gi = even ? gA : oA;
            float gf = even ? gB : oB;
            float gg = even ? oA : gA;
            float go = even ? oB : gB;
            c0 = sigm(gf) * c0 + sigm(gi) * tanh_hw(gg);
            if (even) wo0[u] = sigm(go) * tanh_hw(c0);
        }
        // ---- batch 1 tail ----
        {
            float sA0, sA1, sB0, sB1;
            unpack2(add2(a10, a11), sA0, sA1);
            unpack2(add2(a12, a13), sB0, sB1);
            float gA = (sA0 + sA1) + bsA;
            float gB = (sB0 + sB1) + bsB;
            if (s == 0) {
                gA = __fmaf_rn(-wihA2, qs1, gA);
                gB = __fmaf_rn(-wihB2, qs1, gB);
            }
            float oA = __shfl_xor_sync(0xffffffffu, gA, 1);
            float oB = __shfl_xor_sync(0xffffffffu, gB, 1);
            float gi = even ? gA : oA;
            float gf = even ? gB : oB;
            float gg = even ? oA : gA;
            float go = even ? oB : gB;
            c1 = sigm(gf) * c1 + sigm(gi) * tanh_hw(gg);
            if (even) wo1[u] = sigm(go) * tanh_hw(c1);
        }
        __syncthreads();
    }

    // Tail: y_{T-1} from slot Tn&1 = 0 for both batches.
    if (wid < 2) {
        const float* hr = (const float*)hb4[wid][Tn & 1];
        float yp = hr[lane] * ow0 + hr[lane + 32] * ow1;
        yp += __shfl_xor_sync(0xffffffffu, yp, 16);
        yp += __shfl_xor_sync(0xffffffffu, yp, 8);
        yp += __shfl_xor_sync(0xffffffffu, yp, 4);
        yp += __shfl_xor_sync(0xffffffffu, yp, 2);
        yp += __shfl_xor_sync(0xffffffffu, yp, 1);
        if (lane == 0) {
            float y = yp + ob;
            if (wid == 0) {
                oy0[Tn - 1] = y;
                if (Tn - 1 < sl0) { float d = xbuf[0][Tn - 1] - y; lacc = __fmaf_rn(d, d, lacc); }
                g_partial[b0] = lacc;
            } else {
                oy1[Tn - 1] = y;
                if (Tn - 1 < sl1) { float d = xbuf[1][Tn - 1] - y; lacc = __fmaf_rn(d, d, lacc); }
                g_partial[b1] = lacc;
            }
        }
    }

    // ---- last-CTA deterministic loss finalize ----
    __threadfence();
    if (t == 0) s_last = atomicInc(&g_done, NCTA - 1);   // wraps to 0 each run
    __syncthreads();
    if (s_last == NCTA - 1) {
        __threadfence();
        double    s = 0.0;
        long long c = 0;
        for (int i = t; i < Bn; i += 128) {              // fixed order
            s += (double)g_partial[i];
            c += (long long)seq_lengths[i];
        }
        red_s[t] = s;
        red_c[t] = c;
        __syncthreads();
        for (int off = 64; off; off >>= 1) {             // fixed tree
            if (t < off) {
                red_s[t] += red_s[t + off];
                red_c[t] += red_c[t + off];
            }
            __syncthreads();
        }
        if (t == 0) out[0] = (float)(red_s[0] / (double)red_c[0]);
    }
}

extern "C" void kernel_launch(void* const* d_in, const int* in_sizes, int n_in,
                              void* d_out, int out_size) {
    const float* padded   = (const float*)d_in[0];
    const int*   seql     = (const int*)  d_in[1];
    const float* enc_Wih  = (const float*)d_in[2];
    const float* enc_Whh  = (const float*)d_in[3];
    const float* enc_b    = (const float*)d_in[4];
    const float* enc_linW = (const float*)d_in[5];
    const float* enc_linb = (const float*)d_in[6];
    const float* dec_linW = (const float*)d_in[7];
    const float* dec_linb = (const float*)d_in[8];
    const float* dec_Wih  = (const float*)d_in[9];
    const float* dec_Whh  = (const float*)d_in[10];
    const float* dec_b    = (const float*)d_in[11];
    const float* outW     = (const float*)d_in[12];
    const float* outb     = (const float*)d_in[13];
    float* out = (float*)d_out;

    sort_kernel<<<1, 1024>>>(seql);
    lstm_kernel<<<NCTA, 128>>>(padded, seql,
                               enc_Wih, enc_Whh, enc_b,
                               enc_linW, enc_linb,
                               dec_linW, dec_linb,
                               dec_Wih, dec_Whh, dec_b,
                               outW, outb, out);
}